// round 1
// baseline (speedup 1.0000x reference)
#include <cuda_runtime.h>

#define B_      2
#define C_      192
#define C3_     576
#define H_      256
#define W_      256
#define HW_     65536
#define HEADS_  8
#define SLICE_  8192
#define KSPLIT_ 8

// ---------------- scratch (device globals: allocation-free rule) ----------------
__device__ float g_qkv  [(size_t)B_ * C3_ * HW_];                     // 1x1 conv out   (302 MB)
__device__ float g_qkvdw[(size_t)B_ * C3_ * HW_];                     // depthwise out  (302 MB)
__device__ float g_av   [(size_t)B_ * C_ * HW_];                      // attn @ v       (100 MB)
__device__ float g_gramp[(size_t)KSPLIT_ * B_ * HEADS_ * C_ * C_];    // split-K partials (19 MB)
__device__ float g_attn [(size_t)B_ * HEADS_ * C_ * C_];              // softmaxed attn (2.4 MB)
__device__ float g_invq [B_ * C_ * 8];
__device__ float g_invk [B_ * C_ * 8];

#define FMA16(a4, b4, acc)                                                                   \
    acc[0][0] += a4.x * b4.x; acc[0][1] += a4.x * b4.y; acc[0][2] += a4.x * b4.z; acc[0][3] += a4.x * b4.w; \
    acc[1][0] += a4.y * b4.x; acc[1][1] += a4.y * b4.y; acc[1][2] += a4.y * b4.z; acc[1][3] += a4.y * b4.w; \
    acc[2][0] += a4.z * b4.x; acc[2][1] += a4.z * b4.y; acc[2][2] += a4.z * b4.z; acc[2][3] += a4.z * b4.w; \
    acc[3][0] += a4.w * b4.x; acc[3][1] += a4.w * b4.y; acc[3][2] += a4.w * b4.z; acc[3][3] += a4.w * b4.w;

// ---------------- generic row-major SGEMM: C[M,N] = A[M,K] @ B[K,N] -------------
// block tile 64x64, BK=16, 256 threads, 4x4 microtile. A shared across grid.z.
__global__ __launch_bounds__(256) void sgemm_rrr(
    const float* __restrict__ A, const float* __restrict__ B, float* __restrict__ C,
    int K, int lda, int ldb, int ldc, long long strideB, long long strideC)
{
    const int bn = blockIdx.x * 64;
    const int bm = blockIdx.y * 64;
    B += (long long)blockIdx.z * strideB;
    C += (long long)blockIdx.z * strideC;

    __shared__ float As[16][64];
    __shared__ float Bs[16][64];

    const int tid = threadIdx.x;
    const int tx = tid & 15, ty = tid >> 4;
    const int am = tid >> 2, ak = (tid & 3) << 2;       // A loader: row am, k chunk ak
    const int bk = tid >> 4, bn4 = (tid & 15) << 2;     // B loader: k row bk, col chunk bn4

    float acc[4][4] = {};

    for (int kt = 0; kt < K; kt += 16) {
        float4 av = *(const float4*)&A[(long long)(bm + am) * lda + kt + ak];
        As[ak + 0][am] = av.x; As[ak + 1][am] = av.y;
        As[ak + 2][am] = av.z; As[ak + 3][am] = av.w;
        *(float4*)&Bs[bk][bn4] = *(const float4*)&B[(long long)(kt + bk) * ldb + bn + bn4];
        __syncthreads();
#pragma unroll
        for (int k = 0; k < 16; ++k) {
            float4 a4 = *(const float4*)&As[k][ty << 2];
            float4 b4 = *(const float4*)&Bs[k][tx << 2];
            FMA16(a4, b4, acc);
        }
        __syncthreads();
    }
#pragma unroll
    for (int i = 0; i < 4; ++i)
        *(float4*)&C[(long long)(bm + (ty << 2) + i) * ldc + bn + (tx << 2)] =
            make_float4(acc[i][0], acc[i][1], acc[i][2], acc[i][3]);
}

// ---------------- depthwise 3x3, SAME padding --------------------------------
__global__ __launch_bounds__(256) void dw_kernel(
    const float* __restrict__ in_, const float* __restrict__ dww, float* __restrict__ out_)
{
    const int chg = blockIdx.z;            // b*576 + c
    const int c = chg % C3_;
    const float* in = in_ + ((long long)chg << 16);
    float* op = out_ + ((long long)chg << 16);

    float w[9];
#pragma unroll
    for (int i = 0; i < 9; ++i) w[i] = __ldg(&dww[c * 9 + i]);

    __shared__ float s[34][34];
    const int ox = blockIdx.x * 32 - 1, oy = blockIdx.y * 32 - 1;
    for (int t = threadIdx.x; t < 34 * 34; t += 256) {
        int lx = t % 34, ly = t / 34;
        int gx = ox + lx, gy = oy + ly;
        float v = 0.f;
        if ((unsigned)gx < W_ && (unsigned)gy < H_) v = in[gy * W_ + gx];
        s[ly][lx] = v;
    }
    __syncthreads();

    const int tx = threadIdx.x & 31, ty0 = threadIdx.x >> 5;
#pragma unroll
    for (int r = 0; r < 4; ++r) {
        int ly = ty0 + 8 * r;
        float acc = s[ly + 0][tx + 0] * w[0] + s[ly + 0][tx + 1] * w[1] + s[ly + 0][tx + 2] * w[2]
                  + s[ly + 1][tx + 0] * w[3] + s[ly + 1][tx + 1] * w[4] + s[ly + 1][tx + 2] * w[5]
                  + s[ly + 2][tx + 0] * w[6] + s[ly + 2][tx + 1] * w[7] + s[ly + 2][tx + 2] * w[8];
        op[(blockIdx.y * 32 + ly) * W_ + blockIdx.x * 32 + tx] = acc;
    }
}

// ---------------- per-slice L2 norms of q and k -------------------------------
__global__ __launch_bounds__(256) void norms_kernel(
    const float* __restrict__ qkvdw, float* __restrict__ invq, float* __restrict__ invk)
{
    const int z = blockIdx.x;              // b*192*8 + ch*8 + sl
    const int sl = z & 7;
    const int ch = (z >> 3) % C_;
    const int b = z / (C_ * 8);
    const float4* qp = (const float4*)(qkvdw + ((long long)(b * C3_ + ch) << 16) + (sl << 13));
    const float4* kp = (const float4*)(qkvdw + ((long long)(b * C3_ + C_ + ch) << 16) + (sl << 13));

    float sq = 0.f, sk = 0.f;
    for (int t = threadIdx.x; t < SLICE_ / 4; t += 256) {
        float4 v = qp[t]; sq += v.x * v.x + v.y * v.y + v.z * v.z + v.w * v.w;
        float4 w = kp[t]; sk += w.x * w.x + w.y * w.y + w.z * w.z + w.w * w.w;
    }
#pragma unroll
    for (int o = 16; o > 0; o >>= 1) {
        sq += __shfl_xor_sync(0xffffffffu, sq, o);
        sk += __shfl_xor_sync(0xffffffffu, sk, o);
    }
    __shared__ float r1[8], r2[8];
    if ((threadIdx.x & 31) == 0) { r1[threadIdx.x >> 5] = sq; r2[threadIdx.x >> 5] = sk; }
    __syncthreads();
    if (threadIdx.x == 0) {
        float a = 0.f, c2 = 0.f;
#pragma unroll
        for (int w2 = 0; w2 < 8; ++w2) { a += r1[w2]; c2 += r2[w2]; }
        int idx = (b * C_ + ch) * 8 + sl;
        invq[idx] = 1.f / fmaxf(sqrtf(a), 1e-12f);
        invk[idx] = 1.f / fmaxf(sqrtf(c2), 1e-12f);
    }
}

// ---------------- Gram: q @ k^T (unnormalized), split-K=8 ---------------------
__global__ __launch_bounds__(256) void gram_kernel(
    const float* __restrict__ qkvdw, float* __restrict__ gramp)
{
    const int z = blockIdx.z;
    const int ks = z & 7, bh = z >> 3;
    const int head = bh & 7, b = bh >> 3;
    const int bi = blockIdx.y * 64, bj = blockIdx.x * 64;
    const int kbase = ks * 1024;

    __shared__ float Qs[16][64];
    __shared__ float Ksm[16][64];

    const int tid = threadIdx.x;
    const int tx = tid & 15, ty = tid >> 4;
    const int lr = tid >> 2, lk = (tid & 3) << 2;

    const int qi = bi + lr, kj = bj + lr;
    const float* qrow = qkvdw + ((long long)(b * C3_ + head * 24 + (qi >> 3)) << 16) + ((qi & 7) << 13) + kbase;
    const float* krow = qkvdw + ((long long)(b * C3_ + C_ + head * 24 + (kj >> 3)) << 16) + ((kj & 7) << 13) + kbase;

    float acc[4][4] = {};
    for (int kt = 0; kt < 1024; kt += 16) {
        float4 qv = *(const float4*)(qrow + kt + lk);
        float4 kv = *(const float4*)(krow + kt + lk);
        Qs[lk + 0][lr] = qv.x; Qs[lk + 1][lr] = qv.y; Qs[lk + 2][lr] = qv.z; Qs[lk + 3][lr] = qv.w;
        Ksm[lk + 0][lr] = kv.x; Ksm[lk + 1][lr] = kv.y; Ksm[lk + 2][lr] = kv.z; Ksm[lk + 3][lr] = kv.w;
        __syncthreads();
#pragma unroll
        for (int k = 0; k < 16; ++k) {
            float4 a4 = *(const float4*)&Qs[k][ty << 2];
            float4 b4 = *(const float4*)&Ksm[k][tx << 2];
            FMA16(a4, b4, acc);
        }
        __syncthreads();
    }
    float* op = gramp + ((long long)ks * (B_ * HEADS_) + bh) * (C_ * C_);
#pragma unroll
    for (int i = 0; i < 4; ++i)
        *(float4*)&op[(bi + (ty << 2) + i) * C_ + bj + (tx << 2)] =
            make_float4(acc[i][0], acc[i][1], acc[i][2], acc[i][3]);
}

// ---------------- split-K reduce + normalize scales + softmax -----------------
__global__ void softmax_kernel(
    const float* __restrict__ gramp, const float* __restrict__ invq,
    const float* __restrict__ invk, const float* __restrict__ temp,
    float* __restrict__ attn)
{
    const int i = blockIdx.x % C_;
    const int bh = blockIdx.x / C_;
    const int head = bh & 7, b = bh >> 3;
    const int j = threadIdx.x;              // 192 threads

    const long long base = (long long)bh * (C_ * C_) + i * C_ + j;
    float s = 0.f;
#pragma unroll
    for (int ks = 0; ks < KSPLIT_; ++ks)
        s += gramp[(long long)ks * (B_ * HEADS_ * C_ * C_) + base];

    s *= invq[(b * C_ + head * 24 + (i >> 3)) * 8 + (i & 7)]
       * invk[(b * C_ + head * 24 + (j >> 3)) * 8 + (j & 7)]
       * temp[head];

    __shared__ float red[8];
    float m = s;
#pragma unroll
    for (int o = 16; o > 0; o >>= 1) m = fmaxf(m, __shfl_xor_sync(0xffffffffu, m, o));
    if ((threadIdx.x & 31) == 0) red[threadIdx.x >> 5] = m;
    __syncthreads();
    m = fmaxf(fmaxf(fmaxf(red[0], red[1]), fmaxf(red[2], red[3])), fmaxf(red[4], red[5]));

    float p = expf(s - m);
    float sum = p;
#pragma unroll
    for (int o = 16; o > 0; o >>= 1) sum += __shfl_xor_sync(0xffffffffu, sum, o);
    __syncthreads();
    if ((threadIdx.x & 31) == 0) red[threadIdx.x >> 5] = sum;
    __syncthreads();
    sum = red[0] + red[1] + red[2] + red[3] + red[4] + red[5];

    attn[base] = p / sum;
}

// ---------------- out = attn @ v, written back in (b,c,hw) layout -------------
__global__ __launch_bounds__(256) void av_kernel(
    const float* __restrict__ attn, const float* __restrict__ qkvdw, float* __restrict__ av)
{
    const int bh = blockIdx.z;
    const int head = bh & 7, b = bh >> 3;
    const int bn = blockIdx.x * 64, bi = blockIdx.y * 64;
    const float* A = attn + (long long)bh * (C_ * C_);

    __shared__ float As[16][64];
    __shared__ float Bs[16][64];

    const int tid = threadIdx.x;
    const int tx = tid & 15, ty = tid >> 4;
    const int am = tid >> 2, ak = (tid & 3) << 2;
    const int bk = tid >> 4, bn4 = (tid & 15) << 2;

    float acc[4][4] = {};
    for (int kt = 0; kt < C_; kt += 16) {
        float4 a4l = *(const float4*)&A[(bi + am) * C_ + kt + ak];
        As[ak + 0][am] = a4l.x; As[ak + 1][am] = a4l.y;
        As[ak + 2][am] = a4l.z; As[ak + 3][am] = a4l.w;
        const int d = kt + bk;
        const float* vrow = qkvdw + ((long long)(b * C3_ + 2 * C_ + head * 24 + (d >> 3)) << 16) + ((d & 7) << 13);
        *(float4*)&Bs[bk][bn4] = *(const float4*)&vrow[bn + bn4];
        __syncthreads();
#pragma unroll
        for (int k = 0; k < 16; ++k) {
            float4 a4 = *(const float4*)&As[k][ty << 2];
            float4 b4 = *(const float4*)&Bs[k][tx << 2];
            FMA16(a4, b4, acc);
        }
        __syncthreads();
    }
#pragma unroll
    for (int i = 0; i < 4; ++i) {
        const int r = bi + (ty << 2) + i;
        float* orow = av + ((long long)(b * C_ + head * 24 + (r >> 3)) << 16) + ((r & 7) << 13);
        *(float4*)&orow[bn + (tx << 2)] = make_float4(acc[i][0], acc[i][1], acc[i][2], acc[i][3]);
    }
}

// ---------------- launch -------------------------------------------------------
extern "C" void kernel_launch(void* const* d_in, const int* in_sizes, int n_in,
                              void* d_out, int out_size)
{
    const float* x      = (const float*)d_in[0];
    const float* qkv_w  = (const float*)d_in[1];
    const float* dw_w   = (const float*)d_in[2];
    const float* proj_w = (const float*)d_in[3];
    const float* temp   = (const float*)d_in[4];
    float* out = (float*)d_out;

    float *qkv, *qkvdw, *av, *gramp, *attn, *invq, *invk;
    cudaGetSymbolAddress((void**)&qkv,   g_qkv);
    cudaGetSymbolAddress((void**)&qkvdw, g_qkvdw);
    cudaGetSymbolAddress((void**)&av,    g_av);
    cudaGetSymbolAddress((void**)&gramp, g_gramp);
    cudaGetSymbolAddress((void**)&attn,  g_attn);
    cudaGetSymbolAddress((void**)&invq,  g_invq);
    cudaGetSymbolAddress((void**)&invk,  g_invk);

    // 1) qkv = qkv_w @ x      [576,192] @ [192,65536] per batch
    sgemm_rrr<<<dim3(HW_ / 64, C3_ / 64, B_), 256>>>(
        qkv_w, x, qkv, C_, C_, HW_, HW_,
        (long long)C_ * HW_, (long long)C3_ * HW_);

    // 2) depthwise 3x3
    dw_kernel<<<dim3(W_ / 32, H_ / 32, B_ * C3_), 256>>>(qkv, dw_w, qkvdw);

    // 3) per-slice L2 norms of q and k
    norms_kernel<<<B_ * C_ * 8, 256>>>(qkvdw, invq, invk);

    // 4) Gram partials (split-K = 8)
    gram_kernel<<<dim3(C_ / 64, C_ / 64, B_ * HEADS_ * KSPLIT_), 256>>>(qkvdw, gramp);

    // 5) reduce + scale + softmax
    softmax_kernel<<<B_ * HEADS_ * C_, C_>>>(gramp, invq, invk, temp, attn);

    // 6) attn @ v (written back in (b,c,hw) layout)
    av_kernel<<<dim3(SLICE_ / 64, C_ / 64, B_ * HEADS_), 256>>>(attn, qkvdw, av);

    // 7) out = proj_w @ av     [192,192] @ [192,65536] per batch
    sgemm_rrr<<<dim3(HW_ / 64, C_ / 64, B_), 256>>>(
        proj_w, av, out, C_, C_, HW_, HW_,
        (long long)C_ * HW_, (long long)C_ * HW_);
}